// round 1
// baseline (speedup 1.0000x reference)
#include <cuda_runtime.h>
#include <cuda_fp16.h>

#define SEQ 256
#define VOC 96
#define DD  (SEQ * VOC)   // 24576 dendrites

// Transposed log-weight table: [d][v] in half. 24576*96*2B = 4.5 MB (fits in L2).
__device__ __half g_tab[DD * VOC];

// ---------------------------------------------------------------------------
// Kernel 1: log_w = log(max(2*sigmoid(raw), 1e-8)), transposed (V,D)->(D,V),
// stored as fp16. Tiled through shared memory so both the global read
// (contiguous d per row v) and the global write (contiguous v per row d)
// are coalesced. Row pad 98 halves (49 words, gcd(49,32)=1) -> conflict-free.
// ---------------------------------------------------------------------------
__global__ void transform_kernel(const float* __restrict__ raw) {
    __shared__ __half tile[128][98];
    const int d0 = blockIdx.x * 128;
    const int t  = threadIdx.x;   // 0..127

    #pragma unroll 4
    for (int v = 0; v < VOC; v++) {
        float x = raw[v * DD + d0 + t];
        float w = 2.0f / (1.0f + __expf(-x));
        tile[t][v] = __float2half(logf(fmaxf(w, 1e-8f)));
    }
    __syncthreads();

    __half2* out = reinterpret_cast<__half2*>(g_tab);
    #pragma unroll 4
    for (int i = t; i < 128 * (VOC / 2); i += 128) {
        int dr = i / (VOC / 2);
        int j  = i % (VOC / 2);
        __half2 h = __halves2half2(tile[dr][2 * j], tile[dr][2 * j + 1]);
        out[(d0 + dr) * (VOC / 2) + j] = h;
    }
}

// ---------------------------------------------------------------------------
// Kernel 2: per-sample gather-sum. 96 threads/block = 2 samples x 48 lanes.
// Lane j accumulates classes (2j, 2j+1) via one half2 load per fired position.
// Char values staged in shared so the warp-uniform index compute is cheap and
// the c>0 branch is (nearly) warp-uniform.
// ---------------------------------------------------------------------------
__global__ void gather_kernel(const int* __restrict__ chars,
                              float* __restrict__ out, int B) {
    __shared__ int sc[2 * SEQ];
    const int t     = threadIdx.x;       // 0..95
    const int bbase = blockIdx.x * 2;

    // Cooperatively stage 2 samples of char values
    for (int i = t; i < 2 * SEQ; i += 96) {
        int b = bbase + (i >> 8);
        sc[i] = (b < B) ? chars[b * SEQ + (i & (SEQ - 1))] : 0;
    }
    __syncthreads();

    const int sub = t / 48;              // which of the 2 samples
    const int j   = t - sub * 48;        // half2 lane: classes 2j, 2j+1
    const int b   = bbase + sub;

    const __half2* __restrict__ tab = reinterpret_cast<const __half2*>(g_tab);
    const int* csub = sc + sub * SEQ;

    float a0 = 0.0f, a1 = 0.0f;
    int nact = 0;
    #pragma unroll 8
    for (int s = 0; s < SEQ; s++) {
        int c = csub[s];
        if (c > 0) {
            __half2 h = __ldg(&tab[(s * VOC + (c - 1)) * (VOC / 2) + j]);
            float2 f = __half22float2(h);
            a0 += f.x;
            a1 += f.y;
            nact++;
        }
    }

    if (b < B) {
        float inv = 1.0f / fmaxf((float)nact, 1.0f);
        float2 r;
        r.x = expf(a0 * inv);
        r.y = expf(a1 * inv);
        reinterpret_cast<float2*>(out)[b * (VOC / 2) + j] = r;
    }
}

// ---------------------------------------------------------------------------
extern "C" void kernel_launch(void* const* d_in, const int* in_sizes, int n_in,
                              void* d_out, int out_size) {
    // Identify inputs by element count (robust to metadata ordering):
    // raw_weights has VOC*DD = 2359296 elements; char_values has B*SEQ.
    const int*   chars = nullptr;
    const float* raw   = nullptr;
    int csz = 0;
    if (in_sizes[0] == VOC * DD) {
        raw   = (const float*)d_in[0];
        chars = (const int*)d_in[1];
        csz   = in_sizes[1];
    } else {
        chars = (const int*)d_in[0];
        raw   = (const float*)d_in[1];
        csz   = in_sizes[1] == VOC * DD ? in_sizes[0] : in_sizes[0];
    }
    const int B = csz / SEQ;

    transform_kernel<<<DD / 128, 128>>>(raw);
    gather_kernel<<<(B + 1) / 2, 96>>>(chars, (float*)d_out, B);
}

// round 2
// speedup vs baseline: 2.0620x; 2.0620x over previous
#include <cuda_runtime.h>
#include <cuda_fp16.h>

#define SEQ 256
#define VOC 96
#define DD  (SEQ * VOC)   // 24576 dendrites
#define VH  (VOC / 2)     // 48 half2 per row

// Transposed log-weight table: [d][v] in half. 24576*96*2B = 4.5 MB (fits in L2).
__device__ __half g_tab[DD * VOC];

// ---------------------------------------------------------------------------
// Kernel 1: log_w = log(max(2*sigmoid(raw), 1e-8)) = clamp(ln2 - ln(1+e^-x)),
// transposed (V,D)->(D,V), stored fp16. Tile: 64 d-columns x 96 v per block,
// 256 threads, 384 blocks. Row pad 98 halves (49 words, gcd(49,32)=1).
// ---------------------------------------------------------------------------
__global__ void transform_kernel(const float* __restrict__ raw) {
    __shared__ __half tile[64][98];
    const int d0 = blockIdx.x * 64;
    const int t  = threadIdx.x;   // 0..255

    #pragma unroll
    for (int i = t; i < 64 * VOC; i += 256) {
        int v  = i >> 6;          // i / 64
        int dc = i & 63;          // i % 64
        float x = raw[v * DD + d0 + dc];
        float e = __expf(-x);
        float l = __logf(1.0f + e);
        float r = fmaxf(0.69314718f - l, -18.4206807f);  // clamp at ln(1e-8)
        tile[dc][v] = __float2half(r);
    }
    __syncthreads();

    // Write out: fully contiguous half2 stream (out word idx = d0*48 + i)
    __half2* out = reinterpret_cast<__half2*>(g_tab);
    #pragma unroll
    for (int i = t; i < 64 * VH; i += 256) {
        int dr = i / VH;
        int j  = i % VH;
        __half2 h = *reinterpret_cast<__half2*>(&tile[dr][2 * j]);
        out[(d0 + dr) * VH + j] = h;
    }
}

// ---------------------------------------------------------------------------
// Kernel 2: per-sample gather-sum. 192 threads = 2 samples x 2 seq-halves x
// 48 half2-lanes. Branchless inner loop (offset+weight precomputed in shared)
// so ptxas batches the L2-resident LDGs (MLP=8). Seq-halves combined via smem.
// ---------------------------------------------------------------------------
__global__ void gather_kernel(const int* __restrict__ chars,
                              float* __restrict__ out, int B) {
    __shared__ int   soff[2 * SEQ];
    __shared__ float sw  [2 * SEQ];
    __shared__ float r0[96], r1[96], rn[96];

    const int t     = threadIdx.x;       // 0..191
    const int bbase = blockIdx.x * 2;

    // Stage 2 samples: precompute table word-offset and fired-weight
    for (int i = t; i < 2 * SEQ; i += 192) {
        int b = bbase + (i >> 8);
        int s = i & (SEQ - 1);
        int c = (b < B) ? chars[b * SEQ + s] : 0;
        soff[i] = (s * VOC + max(c - 1, 0)) * VH;
        sw[i]   = (c > 0) ? 1.0f : 0.0f;
    }
    __syncthreads();

    const int sub  = t / 96;             // which sample in block
    const int half = (t / 48) & 1;       // which seq half
    const int j    = t % 48;             // half2 lane -> classes 2j, 2j+1

    const __half2* __restrict__ tab = reinterpret_cast<const __half2*>(g_tab);
    const int base = sub * SEQ + half * (SEQ / 2);

    float a0 = 0.0f, a1 = 0.0f, wn = 0.0f;
    #pragma unroll 8
    for (int s = 0; s < SEQ / 2; s++) {
        int   off = soff[base + s];
        float w   = sw[base + s];
        float2 f  = __half22float2(tab[off + j]);
        a0 = fmaf(f.x, w, a0);
        a1 = fmaf(f.y, w, a1);
        wn += w;
    }

    const int slot = sub * 48 + j;
    if (half == 1) { r0[slot] = a0; r1[slot] = a1; rn[slot] = wn; }
    __syncthreads();
    if (half == 0) {
        a0 += r0[slot];
        a1 += r1[slot];
        wn += rn[slot];
        int b = bbase + sub;
        if (b < B) {
            float inv = 1.0f / fmaxf(wn, 1.0f);
            float2 r;
            r.x = __expf(a0 * inv);
            r.y = __expf(a1 * inv);
            reinterpret_cast<float2*>(out)[b * VH + j] = r;
        }
    }
}

// ---------------------------------------------------------------------------
extern "C" void kernel_launch(void* const* d_in, const int* in_sizes, int n_in,
                              void* d_out, int out_size) {
    // Identify inputs by element count (robust to metadata ordering):
    // raw_weights has VOC*DD = 2359296 elements; char_values has B*SEQ.
    const int*   chars;
    const float* raw;
    int csz;
    if (in_sizes[0] == VOC * DD) {
        raw   = (const float*)d_in[0];
        chars = (const int*)d_in[1];
        csz   = in_sizes[1];
    } else {
        chars = (const int*)d_in[0];
        raw   = (const float*)d_in[1];
        csz   = in_sizes[0];
    }
    const int B = csz / SEQ;

    transform_kernel<<<DD / 64, 256>>>(raw);
    gather_kernel<<<(B + 1) / 2, 192>>>(chars, (float*)d_out, B);
}